// round 7
// baseline (speedup 1.0000x reference)
#include <cuda_runtime.h>
#include <cuda_fp16.h>
#include <cstdint>

#define CK     512
#define VDIM   1024
#define MTOT   131072
#define BM     128
#define BN     256
#define BK     64
#define NCHUNK (CK / BK)       // 8
#define NTHREADS 512

#define A_BYTES     16384      // 128 rows x 128B (fp16 k64)
#define B_BYTES     32768      // 256 rows x 128B
#define SMEM_DYN    (2 * A_BYTES + 3 * B_BYTES + 256)   // 2 A stages + 3 B stages

// fp16 W, converted once (1 MB; L2-resident thereafter)
__device__ __half Wh_g[(size_t)VDIM * CK];

__device__ __forceinline__ float fast_tanh(float x) {
    float y; asm("tanh.approx.f32 %0, %1;" : "=f"(y) : "f"(x)); return y;
}
__device__ __forceinline__ uint32_t smem_u32(const void* p) {
    uint32_t a;
    asm("{ .reg .u64 t; cvta.to.shared.u64 t, %1; cvt.u32.u64 %0, t; }" : "=r"(a) : "l"(p));
    return a;
}
__device__ __forceinline__ uint32_t swz(uint32_t x) { return x ^ ((x >> 3) & 0x70); }
__device__ __forceinline__ void sts128h(uint32_t addr, __half2 a, __half2 b, __half2 c, __half2 d) {
    asm volatile("st.shared.v4.b32 [%0], {%1,%2,%3,%4};"
        :: "r"(addr), "r"(*(uint32_t*)&a), "r"(*(uint32_t*)&b), "r"(*(uint32_t*)&c), "r"(*(uint32_t*)&d) : "memory");
}

#define CP16(s, g) asm volatile("cp.async.cg.shared.global [%0], [%1], 16;" :: "r"(s), "l"(g))
#define CPCOMMIT() asm volatile("cp.async.commit_group;" ::: "memory")

// ---------------- prolog: W fp32 -> fp16 ----------------
__global__ void __launch_bounds__(256) conv_w(const float* __restrict__ W) {
    const int i = blockIdx.x * 256 + threadIdx.x;       // 131072 float4s
    const float4 w = reinterpret_cast<const float4*>(W)[i];
    __half2* o = reinterpret_cast<__half2*>(Wh_g);
    o[2 * i]     = __floats2half2_rn(w.x, w.y);
    o[2 * i + 1] = __floats2half2_rn(w.z, w.w);
}

// ---------------- fused GEMM ----------------
__global__ void __launch_bounds__(NTHREADS)
joiner_gemm(const float* __restrict__ enc, const float* __restrict__ pred,
            const float* __restrict__ bias, float* __restrict__ out)
{
    extern __shared__ char smem_raw[];
    const uint32_t smemBase = (smem_u32(smem_raw) + 127u) & ~127u;
    const uint32_t sA[2] = { smemBase, smemBase + A_BYTES };
    const uint32_t sB0   = smemBase + 2 * A_BYTES;

    const int tid  = threadIdx.x;
    const int lane = tid & 31;
    const int wid  = tid >> 5;
    const int n0 = blockIdx.x * BN;       // x = n-tile (4) -> A-source L2 reuse in wave
    const int m0 = blockIdx.y * BM;       // y = m-tile (1024)
    const int warpM = (wid & 3) * 32;
    const int warpN = (wid >> 2) * 64;

    float acc[2][8][4];
    #pragma unroll
    for (int mt = 0; mt < 2; ++mt)
        #pragma unroll
        for (int nt = 0; nt < 8; ++nt)
            #pragma unroll
            for (int i = 0; i < 4; ++i) acc[mt][nt][i] = 0.0f;

    // ---- A conversion geometry: thread -> rows r, r+64 at column-group c8 ----
    const int rA  = tid >> 3;             // 0..63 (== u_loc)
    const int c8  = tid & 7;              // 8-half group within 64-k chunk
    const float4* encR0 = reinterpret_cast<const float4*>(enc + (size_t)(m0 >> 6) * CK);
    const float4* encR1 = reinterpret_cast<const float4*>(enc + (size_t)((m0 >> 6) + 1) * CK);
    const float4* predR = reinterpret_cast<const float4*>(pred + (size_t)(((m0 >> 14) << 6) | rA) * CK);
    const uint32_t swA0 = swz((uint32_t)(rA * 128 + c8 * 16));
    const uint32_t swA1 = swz((uint32_t)((rA + 64) * 128 + c8 * 16));

    auto convert_a = [&](int c, int s) {
        const int f4 = c * 16 + c8 * 2;
        const float4 p0 = predR[f4],     p1 = predR[f4 + 1];
        const float4 e00 = encR0[f4],    e01 = encR0[f4 + 1];
        const float4 e10 = encR1[f4],    e11 = encR1[f4 + 1];
        sts128h(sA[s] + swA0,
                __floats2half2_rn(fast_tanh(e00.x + p0.x), fast_tanh(e00.y + p0.y)),
                __floats2half2_rn(fast_tanh(e00.z + p0.z), fast_tanh(e00.w + p0.w)),
                __floats2half2_rn(fast_tanh(e01.x + p1.x), fast_tanh(e01.y + p1.y)),
                __floats2half2_rn(fast_tanh(e01.z + p1.z), fast_tanh(e01.w + p1.w)));
        sts128h(sA[s] + swA1,
                __floats2half2_rn(fast_tanh(e10.x + p0.x), fast_tanh(e10.y + p0.y)),
                __floats2half2_rn(fast_tanh(e10.z + p0.z), fast_tanh(e10.w + p0.w)),
                __floats2half2_rn(fast_tanh(e11.x + p1.x), fast_tanh(e11.y + p1.y)),
                __floats2half2_rn(fast_tanh(e11.z + p1.z), fast_tanh(e11.w + p1.w)));
    };

    // ---- B cp.async issue: 4x16B per thread ----
    const __half* gB0 = Wh_g + (size_t)n0 * CK;
    auto issue_b = [&](int c, int s) {
        const uint32_t sb = sB0 + (uint32_t)s * B_BYTES;
        const __half* gB = gB0 + c * BK;
        #pragma unroll
        for (int i = 0; i < 4; ++i) {
            const int q = tid + i * 512;
            const int row = q >> 3, c16 = q & 7;
            CP16(sb + swz((uint32_t)(row * 128 + c16 * 16)), gB + (size_t)row * CK + c16 * 8);
        }
        CPCOMMIT();
    };

    auto compute_stage = [&](int sa_i, int sb_i) {
        const uint32_t sa = sA[sa_i];
        const uint32_t sb = sB0 + (uint32_t)sb_i * B_BYTES;
        const uint32_t kbAoff = (uint32_t)((lane >> 4) << 4);
        const int jgrp = lane >> 3;
        const int r8   = lane & 7;
        const uint32_t bNoff = (uint32_t)((jgrp >> 1) * 8 + r8);
        const uint32_t bKoff = (uint32_t)((jgrp & 1) * 16);
        #pragma unroll
        for (int k16 = 0; k16 < 4; ++k16) {
            uint32_t a[2][4];
            const uint32_t kbA = (uint32_t)(k16 * 32) + kbAoff;
            #pragma unroll
            for (int mt = 0; mt < 2; ++mt) {
                const uint32_t ad = sa + swz((uint32_t)((warpM + mt * 16 + (lane & 15)) * 128) + kbA);
                asm volatile("ldmatrix.sync.aligned.m8n8.x4.shared.b16 {%0,%1,%2,%3}, [%4];"
                    : "=r"(a[mt][0]), "=r"(a[mt][1]), "=r"(a[mt][2]), "=r"(a[mt][3]) : "r"(ad));
            }
            uint32_t b[8][2];
            const uint32_t kbB = (uint32_t)(k16 * 32) + bKoff;
            #pragma unroll
            for (int np = 0; np < 4; ++np) {
                const uint32_t ad = sb + swz((uint32_t)(warpN + np * 16 + bNoff) * 128u + kbB);
                asm volatile("ldmatrix.sync.aligned.m8n8.x4.shared.b16 {%0,%1,%2,%3}, [%4];"
                    : "=r"(b[2 * np][0]), "=r"(b[2 * np][1]), "=r"(b[2 * np + 1][0]), "=r"(b[2 * np + 1][1])
                    : "r"(ad));
            }
            #pragma unroll
            for (int mt = 0; mt < 2; ++mt)
                #pragma unroll
                for (int nt = 0; nt < 8; ++nt)
                    asm volatile(
                        "mma.sync.aligned.m16n8k16.row.col.f32.f16.f16.f32 "
                        "{%0,%1,%2,%3},{%4,%5,%6,%7},{%8,%9},{%0,%1,%2,%3};"
                        : "+f"(acc[mt][nt][0]), "+f"(acc[mt][nt][1]),
                          "+f"(acc[mt][nt][2]), "+f"(acc[mt][nt][3])
                        : "r"(a[mt][0]), "r"(a[mt][1]), "r"(a[mt][2]), "r"(a[mt][3]),
                          "r"(b[nt][0]), "r"(b[nt][1]));
        }
    };

    // ---- prologue ----
    issue_b(0, 0);
    issue_b(1, 1);
    convert_a(0, 0);

    // ---- main loop ----
    #pragma unroll 1
    for (int c = 0; c < NCHUNK; ++c) {
        if (c < NCHUNK - 1) asm volatile("cp.async.wait_group 1;" ::: "memory");
        else                asm volatile("cp.async.wait_group 0;" ::: "memory");
        __syncthreads();                 // A[c%2] converted + B[c%3] landed, visible to all
        compute_stage(c & 1, c % 3);
        if (c + 2 < NCHUNK) issue_b(c + 2, (c + 2) % 3);
        if (c + 1 < NCHUNK) convert_a(c + 1, (c + 1) & 1);   // writes buffer compute isn't reading
    }

    // ---- epilogue: bias + fp32 store ----
    const int gr = lane >> 2;
    const int gc = (lane & 3) * 2;
    #pragma unroll
    for (int mt = 0; mt < 2; ++mt) {
        const int m = m0 + warpM + mt * 16 + gr;
        #pragma unroll
        for (int nt = 0; nt < 8; ++nt) {
            const int n = n0 + warpN + nt * 8 + gc;
            const float2 bb = *reinterpret_cast<const float2*>(bias + n);
            float2 v0, v1;
            v0.x = acc[mt][nt][0] + bb.x; v0.y = acc[mt][nt][1] + bb.y;
            v1.x = acc[mt][nt][2] + bb.x; v1.y = acc[mt][nt][3] + bb.y;
            *reinterpret_cast<float2*>(out + (size_t)m * VDIM + n)       = v0;
            *reinterpret_cast<float2*>(out + (size_t)(m + 8) * VDIM + n) = v1;
        }
    }
}

extern "C" void kernel_launch(void* const* d_in, const int* in_sizes, int n_in,
                              void* d_out, int out_size) {
    const float* enc  = (const float*)d_in[0];   // (8,256,512)
    const float* pred = (const float*)d_in[1];   // (8,64,512)
    const float* W    = (const float*)d_in[2];   // (1024,512)
    const float* b    = (const float*)d_in[3];   // (1024,)
    float* out = (float*)d_out;                  // (8,256,64,1024) fp32

    cudaFuncSetAttribute(joiner_gemm, cudaFuncAttributeMaxDynamicSharedMemorySize, SMEM_DYN);

    conv_w<<<VDIM * CK / 4 / 256, 256>>>(W);     // 512 blocks, ~4.4us
    dim3 grid(VDIM / BN, MTOT / BM);             // (4, 1024)
    joiner_gemm<<<grid, NTHREADS, SMEM_DYN>>>(enc, pred, b, out);
}

// round 8
// speedup vs baseline: 1.1643x; 1.1643x over previous
#include <cuda_runtime.h>
#include <cuda_fp16.h>
#include <cstdint>

#define CK     512
#define VDIM   1024
#define MTOT   131072
#define BM     128
#define BN     256
#define BK     64
#define NCHUNK (CK / BK)       // 8
#define NTHREADS 512

// SMEM layout (bytes from 128-aligned base)
#define SA_OFF  0              // 2 x 16KB fp16 A stages
#define SB_OFF  32768          // 3 x 32KB fp16 B stages
#define SP_OFF  131072         // 3 x 16KB raw fp32 pred stages
#define SE_OFF  180224         // 4KB raw fp32 enc (2 rows x 512 floats)
#define SMEM_DYN (184320 + 256)

// fp16 W, converted once (1 MB; L2-resident thereafter)
__device__ __half Wh_g[(size_t)VDIM * CK];

__device__ __forceinline__ float fast_tanh(float x) {
    float y; asm("tanh.approx.f32 %0, %1;" : "=f"(y) : "f"(x)); return y;
}
__device__ __forceinline__ uint32_t smem_u32(const void* p) {
    uint32_t a;
    asm("{ .reg .u64 t; cvta.to.shared.u64 t, %1; cvt.u32.u64 %0, t; }" : "=r"(a) : "l"(p));
    return a;
}
__device__ __forceinline__ uint32_t swz(uint32_t x) { return x ^ ((x >> 3) & 0x70); }
__device__ __forceinline__ void sts128h(uint32_t addr, __half2 a, __half2 b, __half2 c, __half2 d) {
    asm volatile("st.shared.v4.b32 [%0], {%1,%2,%3,%4};"
        :: "r"(addr), "r"(*(uint32_t*)&a), "r"(*(uint32_t*)&b), "r"(*(uint32_t*)&c), "r"(*(uint32_t*)&d) : "memory");
}
__device__ __forceinline__ float4 lds4(uint32_t addr) {
    float4 v;
    asm volatile("ld.shared.v4.f32 {%0,%1,%2,%3}, [%4];"
        : "=f"(v.x), "=f"(v.y), "=f"(v.z), "=f"(v.w) : "r"(addr));
    return v;
}

#define CP16(s, g) asm volatile("cp.async.cg.shared.global [%0], [%1], 16;" :: "r"(s), "l"(g))
#define CPCOMMIT() asm volatile("cp.async.commit_group;" ::: "memory")

// ---------------- prolog: W fp32 -> fp16 ----------------
__global__ void __launch_bounds__(256) conv_w(const float* __restrict__ W) {
    const int i = blockIdx.x * 256 + threadIdx.x;       // 131072 float4s
    const float4 w = reinterpret_cast<const float4*>(W)[i];
    __half2* o = reinterpret_cast<__half2*>(Wh_g);
    o[2 * i]     = __floats2half2_rn(w.x, w.y);
    o[2 * i + 1] = __floats2half2_rn(w.z, w.w);
}

// ---------------- fused GEMM ----------------
__global__ void __launch_bounds__(NTHREADS)
joiner_gemm(const float* __restrict__ enc, const float* __restrict__ pred,
            const float* __restrict__ bias, float* __restrict__ out)
{
    extern __shared__ char smem_raw[];
    const uint32_t smemBase = (smem_u32(smem_raw) + 127u) & ~127u;

    const int tid  = threadIdx.x;
    const int lane = tid & 31;
    const int wid  = tid >> 5;
    const int n0 = blockIdx.x * BN;       // x = n-tile (4) -> source L2 reuse within wave
    const int m0 = blockIdx.y * BM;       // y = m-tile (1024)
    const int warpM = (wid & 3) * 32;
    const int warpN = (wid >> 2) * 64;

    float acc[2][8][4];
    #pragma unroll
    for (int mt = 0; mt < 2; ++mt)
        #pragma unroll
        for (int nt = 0; nt < 8; ++nt)
            #pragma unroll
            for (int i = 0; i < 4; ++i) acc[mt][nt][i] = 0.0f;

    // ---- raw staging sources ----
    const float* predBase = pred + (size_t)((m0 >> 14) << 6) * CK;   // 64 u-rows
    const float* encBase  = enc + (size_t)(m0 >> 6) * CK;            // 2 t-rows
    const __half* gB0 = Wh_g + (size_t)n0 * CK;

    // cp.async raw pred chunk: 1024 x 16B, 2 per thread
    auto issue_pred = [&](int c, int s) {
        const uint32_t sp = smemBase + SP_OFF + (uint32_t)s * 16384;
        #pragma unroll
        for (int i = 0; i < 2; ++i) {
            const int q = tid + i * 512;
            const int row = q >> 4, c16 = q & 15;
            CP16(sp + (uint32_t)(row * 256 + c16 * 16),
                 predBase + (size_t)row * CK + c * BK + c16 * 4);
        }
    };
    // cp.async raw enc (whole K, once): 256 x 16B
    auto issue_enc = [&]() {
        if (tid < 256) {
            const int row = tid >> 7, c16 = tid & 127;
            CP16(smemBase + SE_OFF + (uint32_t)tid * 16,
                 encBase + (size_t)row * CK + c16 * 4);
        }
    };
    // cp.async B chunk: 2048 x 16B, 4 per thread
    auto issue_b = [&](int c, int s) {
        const uint32_t sb = smemBase + SB_OFF + (uint32_t)s * 32768;
        const __half* gB = gB0 + c * BK;
        #pragma unroll
        for (int i = 0; i < 4; ++i) {
            const int q = tid + i * 512;
            const int row = q >> 3, c16 = q & 7;
            CP16(sb + swz((uint32_t)(row * 128 + c16 * 16)), gB + (size_t)row * CK + c16 * 8);
        }
    };

    // ---- A convert: SMEM raw -> tanh -> fp16 swizzled A stage ----
    const int rA = tid >> 3;              // 0..63 (u row)
    const int c8 = tid & 7;               // 8-float group within 64-k chunk
    const uint32_t swA0 = swz((uint32_t)(rA * 128 + c8 * 16));
    const uint32_t swA1 = swz((uint32_t)((rA + 64) * 128 + c8 * 16));
    auto convert_a = [&](int c, int sp_i, int sa_i) {
        const uint32_t sp  = smemBase + SP_OFF + (uint32_t)sp_i * 16384 + (uint32_t)(rA * 256 + c8 * 32);
        const uint32_t se  = smemBase + SE_OFF + (uint32_t)(c * 256 + c8 * 32);
        const uint32_t sa  = smemBase + SA_OFF + (uint32_t)sa_i * 16384;
        const float4 p0  = lds4(sp),        p1  = lds4(sp + 16);
        const float4 e00 = lds4(se),        e01 = lds4(se + 16);
        const float4 e10 = lds4(se + 2048), e11 = lds4(se + 2064);
        sts128h(sa + swA0,
                __floats2half2_rn(fast_tanh(e00.x + p0.x), fast_tanh(e00.y + p0.y)),
                __floats2half2_rn(fast_tanh(e00.z + p0.z), fast_tanh(e00.w + p0.w)),
                __floats2half2_rn(fast_tanh(e01.x + p1.x), fast_tanh(e01.y + p1.y)),
                __floats2half2_rn(fast_tanh(e01.z + p1.z), fast_tanh(e01.w + p1.w)));
        sts128h(sa + swA1,
                __floats2half2_rn(fast_tanh(e10.x + p0.x), fast_tanh(e10.y + p0.y)),
                __floats2half2_rn(fast_tanh(e10.z + p0.z), fast_tanh(e10.w + p0.w)),
                __floats2half2_rn(fast_tanh(e11.x + p1.x), fast_tanh(e11.y + p1.y)),
                __floats2half2_rn(fast_tanh(e11.z + p1.z), fast_tanh(e11.w + p1.w)));
    };

    auto compute_stage = [&](int sa_i, int sb_i) {
        const uint32_t sa = smemBase + SA_OFF + (uint32_t)sa_i * 16384;
        const uint32_t sb = smemBase + SB_OFF + (uint32_t)sb_i * 32768;
        const uint32_t kbAoff = (uint32_t)((lane >> 4) << 4);
        const int jgrp = lane >> 3;
        const int r8   = lane & 7;
        const uint32_t bNoff = (uint32_t)((jgrp >> 1) * 8 + r8);
        const uint32_t bKoff = (uint32_t)((jgrp & 1) * 16);
        #pragma unroll
        for (int k16 = 0; k16 < 4; ++k16) {
            uint32_t a[2][4];
            const uint32_t kbA = (uint32_t)(k16 * 32) + kbAoff;
            #pragma unroll
            for (int mt = 0; mt < 2; ++mt) {
                const uint32_t ad = sa + swz((uint32_t)((warpM + mt * 16 + (lane & 15)) * 128) + kbA);
                asm volatile("ldmatrix.sync.aligned.m8n8.x4.shared.b16 {%0,%1,%2,%3}, [%4];"
                    : "=r"(a[mt][0]), "=r"(a[mt][1]), "=r"(a[mt][2]), "=r"(a[mt][3]) : "r"(ad));
            }
            uint32_t b[8][2];
            const uint32_t kbB = (uint32_t)(k16 * 32) + bKoff;
            #pragma unroll
            for (int np = 0; np < 4; ++np) {
                const uint32_t ad = sb + swz((uint32_t)(warpN + np * 16 + bNoff) * 128u + kbB);
                asm volatile("ldmatrix.sync.aligned.m8n8.x4.shared.b16 {%0,%1,%2,%3}, [%4];"
                    : "=r"(b[2 * np][0]), "=r"(b[2 * np][1]), "=r"(b[2 * np + 1][0]), "=r"(b[2 * np + 1][1])
                    : "r"(ad));
            }
            #pragma unroll
            for (int mt = 0; mt < 2; ++mt)
                #pragma unroll
                for (int nt = 0; nt < 8; ++nt)
                    asm volatile(
                        "mma.sync.aligned.m16n8k16.row.col.f32.f16.f16.f32 "
                        "{%0,%1,%2,%3},{%4,%5,%6,%7},{%8,%9},{%0,%1,%2,%3};"
                        : "+f"(acc[mt][nt][0]), "+f"(acc[mt][nt][1]),
                          "+f"(acc[mt][nt][2]), "+f"(acc[mt][nt][3])
                        : "r"(a[mt][0]), "r"(a[mt][1]), "r"(a[mt][2]), "r"(a[mt][3]),
                          "r"(b[nt][0]), "r"(b[nt][1]));
        }
    };

    // ---- prologue: groups [enc+P0][B0][P1][B1] ----
    issue_enc(); issue_pred(0, 0); CPCOMMIT();
    issue_b(0, 0);                 CPCOMMIT();
    issue_pred(1, 1);              CPCOMMIT();
    issue_b(1, 1);                 CPCOMMIT();
    asm volatile("cp.async.wait_group 3;" ::: "memory");   // enc + P0 landed
    __syncthreads();
    convert_a(0, 0, 0);

    // ---- main loop ----
    #pragma unroll 1
    for (int c = 0; c < NCHUNK; ++c) {
        // drain all but newest group: guarantees B(c) and P(c+1) landed
        if (c < NCHUNK - 1) asm volatile("cp.async.wait_group 1;" ::: "memory");
        else                asm volatile("cp.async.wait_group 0;" ::: "memory");
        __syncthreads();
        compute_stage(c & 1, c % 3);
        if (c + 2 < NCHUNK) {
            issue_pred(c + 2, (c + 2) % 3); CPCOMMIT();
            issue_b(c + 2, (c + 2) % 3);    CPCOMMIT();
        }
        if (c + 1 < NCHUNK) convert_a(c + 1, (c + 1) % 3, (c + 1) & 1);
    }

    // ---- epilogue: bias + fp32 store ----
    const int gr = lane >> 2;
    const int gc = (lane & 3) * 2;
    #pragma unroll
    for (int mt = 0; mt < 2; ++mt) {
        const int m = m0 + warpM + mt * 16 + gr;
        #pragma unroll
        for (int nt = 0; nt < 8; ++nt) {
            const int n = n0 + warpN + nt * 8 + gc;
            const float2 bb = *reinterpret_cast<const float2*>(bias + n);
            float2 v0, v1;
            v0.x = acc[mt][nt][0] + bb.x; v0.y = acc[mt][nt][1] + bb.y;
            v1.x = acc[mt][nt][2] + bb.x; v1.y = acc[mt][nt][3] + bb.y;
            *reinterpret_cast<float2*>(out + (size_t)m * VDIM + n)       = v0;
            *reinterpret_cast<float2*>(out + (size_t)(m + 8) * VDIM + n) = v1;
        }
    }
}

extern "C" void kernel_launch(void* const* d_in, const int* in_sizes, int n_in,
                              void* d_out, int out_size) {
    const float* enc  = (const float*)d_in[0];   // (8,256,512)
    const float* pred = (const float*)d_in[1];   // (8,64,512)
    const float* W    = (const float*)d_in[2];   // (1024,512)
    const float* b    = (const float*)d_in[3];   // (1024,)
    float* out = (float*)d_out;                  // (8,256,64,1024) fp32

    cudaFuncSetAttribute(joiner_gemm, cudaFuncAttributeMaxDynamicSharedMemorySize, SMEM_DYN);

    conv_w<<<VDIM * CK / 4 / 256, 256>>>(W);     // 512 blocks, ~4.4us
    dim3 grid(VDIM / BN, MTOT / BM);             // (4, 1024)
    joiner_gemm<<<grid, NTHREADS, SMEM_DYN>>>(enc, pred, b, out);
}

// round 9
// speedup vs baseline: 1.3603x; 1.1684x over previous
#include <cuda_runtime.h>
#include <cuda_fp16.h>
#include <cstdint>

#define CK     512
#define VDIM   1024
#define MTOT   131072
#define BM     128
#define BN     128
#define BK     64
#define NCHUNK (CK / BK)       // 8
#define NTHREADS 256

#define A_BYTES     16384      // 128 rows x 128B fp16
#define STAGE_BYTES 32768      // A 16KB + B 16KB
#define SMEM_DYN    (3 * STAGE_BYTES + 256)   // 96KB + pad -> 2 CTAs/SM

// fp16 scratch: tanh(enc+pred) precomputed once, W converted once.
__device__ __half Ah_g[(size_t)MTOT * CK];   // 128 MB
__device__ __half Wh_g[(size_t)VDIM * CK];   // 1 MB

__device__ __forceinline__ float fast_tanh(float x) {
    float y; asm("tanh.approx.f32 %0, %1;" : "=f"(y) : "f"(x)); return y;
}
__device__ __forceinline__ uint32_t smem_u32(const void* p) {
    uint32_t a;
    asm("{ .reg .u64 t; cvta.to.shared.u64 t, %1; cvt.u32.u64 %0, t; }" : "=r"(a) : "l"(p));
    return a;
}
__device__ __forceinline__ uint32_t swz(uint32_t x) { return x ^ ((x >> 3) & 0x70); }

#define CP16(s, g) asm volatile("cp.async.cg.shared.global [%0], [%1], 16;" :: "r"(s), "l"(g))
#define CPCOMMIT() asm volatile("cp.async.commit_group;" ::: "memory")

// ---------------- prolog kernels ----------------
__global__ void __launch_bounds__(256) conv_w(const float* __restrict__ W) {
    const int i = blockIdx.x * 256 + threadIdx.x;       // 131072 float4s
    const float4 w = reinterpret_cast<const float4*>(W)[i];
    __half2* o = reinterpret_cast<__half2*>(Wh_g);
    o[2 * i]     = __floats2half2_rn(w.x, w.y);
    o[2 * i + 1] = __floats2half2_rn(w.z, w.w);
}

__global__ void __launch_bounds__(256) conv_a(const float* __restrict__ enc,
                                              const float* __restrict__ pred) {
    const int g = blockIdx.x * 256 + threadIdx.x;       // float4 id
    const int m = g >> 7;
    const int t = g & 127;
    const float4 e = reinterpret_cast<const float4*>(enc  + (size_t)(m >> 6) * CK)[t];
    const float4 p = reinterpret_cast<const float4*>(pred + (size_t)(((m >> 14) << 6) | (m & 63)) * CK)[t];
    __half2 h0 = __floats2half2_rn(fast_tanh(e.x + p.x), fast_tanh(e.y + p.y));
    __half2 h1 = __floats2half2_rn(fast_tanh(e.z + p.z), fast_tanh(e.w + p.w));
    __half2* o = reinterpret_cast<__half2*>(Ah_g);
    o[2 * (size_t)g]     = h0;
    o[2 * (size_t)g + 1] = h1;
}

// ---------------- main GEMM: 128x128 tile, 8 warps, 2 CTAs/SM ----------------
__global__ void __launch_bounds__(NTHREADS, 2)
joiner_gemm(const float* __restrict__ bias, float* __restrict__ out)
{
    extern __shared__ char smem_raw[];
    const uint32_t smemBase = (smem_u32(smem_raw) + 127u) & ~127u;

    const int tid  = threadIdx.x;
    const int lane = tid & 31;
    const int wid  = tid >> 5;
    const int n0 = blockIdx.x * BN;       // x = n-tile (8) -> A L2 reuse within wave
    const int m0 = blockIdx.y * BM;       // y = m-tile (1024)
    const int warpM = (wid & 1) * 64;     // 2 warp-rows of 64
    const int warpN = (wid >> 1) * 32;    // 4 warp-cols of 32

    float acc[4][4][4];
    #pragma unroll
    for (int mt = 0; mt < 4; ++mt)
        #pragma unroll
        for (int nt = 0; nt < 4; ++nt)
            #pragma unroll
            for (int i = 0; i < 4; ++i) acc[mt][nt][i] = 0.0f;

    const __half* gA0 = Ah_g + (size_t)m0 * CK;
    const __half* gB0 = Wh_g + (size_t)n0 * CK;

    // ---- cp.async stage issue: A 4x16B + B 4x16B per thread ----
    auto issue_stage = [&](int c, int s) {
        const uint32_t sa = smemBase + (uint32_t)s * STAGE_BYTES;
        const uint32_t sb = sa + A_BYTES;
        const __half* gA = gA0 + c * BK;
        const __half* gB = gB0 + c * BK;
        #pragma unroll
        for (int i = 0; i < 4; ++i) {
            const int q = tid + i * 256;
            const int row = q >> 3, c16 = q & 7;
            CP16(sa + swz((uint32_t)(row * 128 + c16 * 16)), gA + (size_t)row * CK + c16 * 8);
        }
        #pragma unroll
        for (int i = 0; i < 4; ++i) {
            const int q = tid + i * 256;
            const int row = q >> 3, c16 = q & 7;
            CP16(sb + swz((uint32_t)(row * 128 + c16 * 16)), gB + (size_t)row * CK + c16 * 8);
        }
        CPCOMMIT();
    };

    auto compute_stage = [&](int s) {
        const uint32_t sa = smemBase + (uint32_t)s * STAGE_BYTES;
        const uint32_t sb = sa + A_BYTES;
        // A: lanes 0-15 -> 16 rows, k-half 0; lanes 16-31 -> k-half 1
        const uint32_t kbAoff = (uint32_t)((lane >> 4) << 4);
        // B (non-trans): lane group j=lane/8 -> matrix j = (n-block j/2, k-half j&1)
        const int jgrp = lane >> 3;
        const uint32_t bNoff = (uint32_t)((jgrp >> 1) * 8 + (lane & 7));
        const uint32_t bKoff = (uint32_t)((jgrp & 1) * 16);
        #pragma unroll
        for (int k16 = 0; k16 < 4; ++k16) {
            uint32_t a[4][4];
            const uint32_t kbA = (uint32_t)(k16 * 32) + kbAoff;
            #pragma unroll
            for (int mt = 0; mt < 4; ++mt) {
                const uint32_t ad = sa + swz((uint32_t)((warpM + mt * 16 + (lane & 15)) * 128) + kbA);
                asm volatile("ldmatrix.sync.aligned.m8n8.x4.shared.b16 {%0,%1,%2,%3}, [%4];"
                    : "=r"(a[mt][0]), "=r"(a[mt][1]), "=r"(a[mt][2]), "=r"(a[mt][3]) : "r"(ad));
            }
            uint32_t b[4][2];
            const uint32_t kbB = (uint32_t)(k16 * 32) + bKoff;
            #pragma unroll
            for (int np = 0; np < 2; ++np) {
                const uint32_t ad = sb + swz((uint32_t)(warpN + np * 16 + bNoff) * 128u + kbB);
                asm volatile("ldmatrix.sync.aligned.m8n8.x4.shared.b16 {%0,%1,%2,%3}, [%4];"
                    : "=r"(b[2 * np][0]), "=r"(b[2 * np][1]), "=r"(b[2 * np + 1][0]), "=r"(b[2 * np + 1][1])
                    : "r"(ad));
            }
            #pragma unroll
            for (int mt = 0; mt < 4; ++mt)
                #pragma unroll
                for (int nt = 0; nt < 4; ++nt)
                    asm volatile(
                        "mma.sync.aligned.m16n8k16.row.col.f32.f16.f16.f32 "
                        "{%0,%1,%2,%3},{%4,%5,%6,%7},{%8,%9},{%0,%1,%2,%3};"
                        : "+f"(acc[mt][nt][0]), "+f"(acc[mt][nt][1]),
                          "+f"(acc[mt][nt][2]), "+f"(acc[mt][nt][3])
                        : "r"(a[mt][0]), "r"(a[mt][1]), "r"(a[mt][2]), "r"(a[mt][3]),
                          "r"(b[nt][0]), "r"(b[nt][1]));
        }
    };

    issue_stage(0, 0);
    issue_stage(1, 1);

    #pragma unroll 1
    for (int c = 0; c < NCHUNK; ++c) {
        if (c < NCHUNK - 1) asm volatile("cp.async.wait_group 1;" ::: "memory");
        else                asm volatile("cp.async.wait_group 0;" ::: "memory");
        __syncthreads();
        compute_stage(c % 3);
        if (c + 2 < NCHUNK) issue_stage(c + 2, (c + 2) % 3);
    }

    // ---- epilogue: bias + fp32 store ----
    const int gr = lane >> 2;
    const int gc = (lane & 3) * 2;
    #pragma unroll
    for (int mt = 0; mt < 4; ++mt) {
        const int m = m0 + warpM + mt * 16 + gr;
        #pragma unroll
        for (int nt = 0; nt < 4; ++nt) {
            const int n = n0 + warpN + nt * 8 + gc;
            const float2 bb = *reinterpret_cast<const float2*>(bias + n);
            float2 v0, v1;
            v0.x = acc[mt][nt][0] + bb.x; v0.y = acc[mt][nt][1] + bb.y;
            v1.x = acc[mt][nt][2] + bb.x; v1.y = acc[mt][nt][3] + bb.y;
            *reinterpret_cast<float2*>(out + (size_t)m * VDIM + n)       = v0;
            *reinterpret_cast<float2*>(out + (size_t)(m + 8) * VDIM + n) = v1;
        }
    }
}

extern "C" void kernel_launch(void* const* d_in, const int* in_sizes, int n_in,
                              void* d_out, int out_size) {
    const float* enc  = (const float*)d_in[0];   // (8,256,512)
    const float* pred = (const float*)d_in[1];   // (8,64,512)
    const float* W    = (const float*)d_in[2];   // (1024,512)
    const float* b    = (const float*)d_in[3];   // (1024,)
    float* out = (float*)d_out;                  // (8,256,64,1024) fp32

    cudaFuncSetAttribute(joiner_gemm, cudaFuncAttributeMaxDynamicSharedMemorySize, SMEM_DYN);

    conv_w<<<VDIM * CK / 4 / 256, 256>>>(W);                   // 512 blocks
    conv_a<<<(size_t)MTOT * CK / 4 / 256, 256>>>(enc, pred);   // 65536 blocks
    dim3 grid(VDIM / BN, MTOT / BM);                           // (8, 1024)
    joiner_gemm<<<grid, NTHREADS, SMEM_DYN>>>(b, out);
}